// round 2
// baseline (speedup 1.0000x reference)
#include <cuda_runtime.h>
#include <cuda_bf16.h>
#include <cstddef>

// Problem constants (fixed shapes)
#define NWIN   4096
#define TT     49
#define DIM    384
#define HEADS  12
#define HD     32
#define NQKV   1152              // 3*DIM
#define MROWS  (NWIN * TT)       // 200704
#define SCALE  0.17677669529663687f   // 1/sqrt(32)
#define EPS    1e-6f

// ---------------------------------------------------------------------------
// Scratch (device globals: allocation-free per harness rules)
// ---------------------------------------------------------------------------
__device__ float g_qkv[(size_t)MROWS * NQKV];   // 924.8 MB
__device__ float g_ctx[(size_t)MROWS * DIM];    // 308.3 MB
__device__ float g_bias[HEADS * TT * TT];       // 115 KB

// ---------------------------------------------------------------------------
// Bias gather: g_bias[h][i][j] = bias_table[rel_index[i][j]][h]
// ---------------------------------------------------------------------------
__global__ void gather_bias_kernel(const float* __restrict__ bt,
                                   const int* __restrict__ ri,
                                   float* __restrict__ ob) {
    int idx = blockIdx.x * blockDim.x + threadIdx.x;
    if (idx < HEADS * TT * TT) {
        int h = idx / (TT * TT);
        int p = idx - h * (TT * TT);
        ob[idx] = bt[ri[p] * HEADS + h];
    }
}

// ---------------------------------------------------------------------------
// SGEMM: C[M,N] = A[M,K] @ B[N,K]^T (+bias[n]), fp32, 128x128x16 tiles,
// 256 threads, 8x8 register tile per thread. All dims divide tiles exactly.
// ---------------------------------------------------------------------------
template<bool ADD_BIAS>
__global__ __launch_bounds__(256, 2)
void sgemm_nt_kernel(const float* __restrict__ A, const float* __restrict__ B,
                     const float* __restrict__ bias, float* __restrict__ C,
                     int M, int N, int K) {
    __shared__ float As[16][132];   // +4 pad: reduce store bank conflicts
    __shared__ float Bs[16][132];

    const int tid = threadIdx.x;
    const int bm = blockIdx.y * 128;
    const int bn = blockIdx.x * 128;
    const int ty = tid >> 4;        // 0..15 -> row group
    const int tx = tid & 15;        // 0..15 -> col group

    float acc[8][8];
#pragma unroll
    for (int i = 0; i < 8; i++)
#pragma unroll
        for (int j = 0; j < 8; j++) acc[i][j] = 0.f;

    const float* Ab = A + (size_t)bm * K;
    const float* Bb = B + (size_t)bn * K;

    for (int kt = 0; kt < K; kt += 16) {
#pragma unroll
        for (int l = 0; l < 2; l++) {
            int v   = tid + l * 256;     // 0..511 float4 slots
            int row = v >> 2;            // 0..127
            int k0  = (v & 3) * 4;       // 0,4,8,12
            float4 a = *(const float4*)(Ab + (size_t)row * K + kt + k0);
            As[k0 + 0][row] = a.x; As[k0 + 1][row] = a.y;
            As[k0 + 2][row] = a.z; As[k0 + 3][row] = a.w;
            float4 b = *(const float4*)(Bb + (size_t)row * K + kt + k0);
            Bs[k0 + 0][row] = b.x; Bs[k0 + 1][row] = b.y;
            Bs[k0 + 2][row] = b.z; Bs[k0 + 3][row] = b.w;
        }
        __syncthreads();
#pragma unroll
        for (int k = 0; k < 16; k++) {
            float ra[8], rb[8];
            *(float4*)(ra)     = *(const float4*)&As[k][ty * 8];
            *(float4*)(ra + 4) = *(const float4*)&As[k][ty * 8 + 4];
            *(float4*)(rb)     = *(const float4*)&Bs[k][tx * 8];
            *(float4*)(rb + 4) = *(const float4*)&Bs[k][tx * 8 + 4];
#pragma unroll
            for (int i = 0; i < 8; i++)
#pragma unroll
                for (int j = 0; j < 8; j++)
                    acc[i][j] += ra[i] * rb[j];
        }
        __syncthreads();
    }

#pragma unroll
    for (int i = 0; i < 8; i++) {
        int gm = bm + ty * 8 + i;
        float* Crow = C + (size_t)gm * N + bn + tx * 8;
#pragma unroll
        for (int j = 0; j < 8; j += 4) {
            float4 r = make_float4(acc[i][j], acc[i][j + 1],
                                   acc[i][j + 2], acc[i][j + 3]);
            if (ADD_BIAS) {
                int n0 = bn + tx * 8 + j;
                r.x += bias[n0];     r.y += bias[n0 + 1];
                r.z += bias[n0 + 2]; r.w += bias[n0 + 3];
            }
            *(float4*)(Crow + j) = r;
        }
    }
}

// ---------------------------------------------------------------------------
// Fused attention: one block per (window, head). 64 threads (49 active for
// compute phases). rmsnorm(q,k) -> S = scale*q@k^T + bias -> softmax -> S@v.
// ---------------------------------------------------------------------------
__global__ __launch_bounds__(64)
void win_attn_kernel(const float* __restrict__ qkv,
                     const float* __restrict__ qn_w,
                     const float* __restrict__ kn_w,
                     const float* __restrict__ biasg,
                     float* __restrict__ ctx) {
    const int b = blockIdx.x;
    const int h = blockIdx.y;
    const int tid = threadIdx.x;

    __shared__ float qs[TT][36];   // stride 36: breaks row-load bank conflicts
    __shared__ float ks[TT][36];
    __shared__ float vs[TT][36];
    __shared__ float S[TT][TT];
    __shared__ float nwq[HD], nwk[HD];

    if (tid < HD) { nwq[tid] = qn_w[tid]; nwk[tid] = kn_w[tid]; }

    const float* base = qkv + (size_t)b * TT * NQKV + h * HD;
    // 392 float4 per matrix (49 rows x 8 float4)
    for (int v4 = tid; v4 < TT * 8; v4 += 64) {
        int i = v4 >> 3, dv = v4 & 7;
        const float* rp = base + (size_t)i * NQKV + dv * 4;
        float4 q  = *(const float4*)(rp);
        float4 k  = *(const float4*)(rp + DIM);
        float4 vv = *(const float4*)(rp + 2 * DIM);
        *(float4*)&qs[i][dv * 4] = q;
        *(float4*)&ks[i][dv * 4] = k;
        *(float4*)&vs[i][dv * 4] = vv;
    }
    __syncthreads();

    float qreg[HD];
    if (tid < TT) {
        float ssq = 0.f, ssk = 0.f;
#pragma unroll
        for (int d = 0; d < HD; d++) {
            float q = qs[tid][d]; qreg[d] = q; ssq += q * q;
            float k = ks[tid][d]; ssk += k * k;
        }
        float rq = rsqrtf(ssq * (1.f / HD) + EPS);
        float rk = rsqrtf(ssk * (1.f / HD) + EPS);
#pragma unroll
        for (int d = 0; d < HD; d++) {
            qreg[d] = qreg[d] * rq * nwq[d];
            ks[tid][d] *= rk * nwk[d];
        }
    }
    __syncthreads();   // all k rows normalized before cross-row reads

    if (tid < TT) {
        const float* brow = biasg + ((size_t)h * TT + tid) * TT;
        float mx = -1e30f;
        for (int j = 0; j < TT; j++) {
            float s = 0.f;
#pragma unroll
            for (int dv = 0; dv < 8; dv++) {
                float4 kk = *(const float4*)&ks[j][dv * 4];  // broadcast
                s += qreg[dv * 4]     * kk.x + qreg[dv * 4 + 1] * kk.y
                   + qreg[dv * 4 + 2] * kk.z + qreg[dv * 4 + 3] * kk.w;
            }
            s = s * SCALE + brow[j];
            S[tid][j] = s;
            mx = fmaxf(mx, s);
        }
        float sum = 0.f;
        for (int j = 0; j < TT; j++) {
            float e = __expf(S[tid][j] - mx);
            S[tid][j] = e;
            sum += e;
        }
        float inv = 1.f / sum;

        float o[HD];
#pragma unroll
        for (int d = 0; d < HD; d++) o[d] = 0.f;
        for (int j = 0; j < TT; j++) {
            float p = S[tid][j];
#pragma unroll
            for (int dv = 0; dv < 8; dv++) {
                float4 vv = *(const float4*)&vs[j][dv * 4];  // broadcast
                o[dv * 4]     += p * vv.x; o[dv * 4 + 1] += p * vv.y;
                o[dv * 4 + 2] += p * vv.z; o[dv * 4 + 3] += p * vv.w;
            }
        }
        float* crow = ctx + ((size_t)b * TT + tid) * DIM + h * HD;
#pragma unroll
        for (int dv = 0; dv < 8; dv++) {
            float4 r = make_float4(o[dv * 4] * inv, o[dv * 4 + 1] * inv,
                                   o[dv * 4 + 2] * inv, o[dv * 4 + 3] * inv);
            *(float4*)(crow + dv * 4) = r;
        }
    }
}

// ---------------------------------------------------------------------------
// Launch
// ---------------------------------------------------------------------------
extern "C" void kernel_launch(void* const* d_in, const int* in_sizes, int n_in,
                              void* d_out, int out_size) {
    const float* x          = (const float*)d_in[0];
    const float* qkv_w      = (const float*)d_in[1];
    const float* q_norm_w   = (const float*)d_in[2];
    const float* k_norm_w   = (const float*)d_in[3];
    const float* proj_w     = (const float*)d_in[4];
    const float* proj_b     = (const float*)d_in[5];
    const float* bias_table = (const float*)d_in[6];
    const int*   rel_index  = (const int*)d_in[7];
    float* out = (float*)d_out;

    float *qkvb, *ctxb, *biasb;
    cudaGetSymbolAddress((void**)&qkvb, g_qkv);
    cudaGetSymbolAddress((void**)&ctxb, g_ctx);
    cudaGetSymbolAddress((void**)&biasb, g_bias);

    // 1) bias gather (independent of qkv GEMM; default stream serializes, fine)
    gather_bias_kernel<<<(HEADS * TT * TT + 255) / 256, 256>>>(bias_table, rel_index, biasb);

    // 2) qkv = x @ qkv_w^T   [200704 x 1152]
    {
        dim3 grid(NQKV / 128, MROWS / 128);
        sgemm_nt_kernel<false><<<grid, 256>>>(x, qkv_w, nullptr, qkvb,
                                              MROWS, NQKV, DIM);
    }

    // 3) fused windowed attention -> ctx [200704 x 384]
    {
        dim3 grid(NWIN, HEADS);
        win_attn_kernel<<<grid, 64>>>(qkvb, q_norm_w, k_norm_w, biasb, ctxb);
    }

    // 4) out = ctx @ proj_w^T + proj_b
    {
        dim3 grid(DIM / 128, MROWS / 128);
        sgemm_nt_kernel<true><<<grid, 256>>>(ctxb, proj_w, proj_b, out,
                                             MROWS, DIM, DIM);
    }
}

// round 4
// speedup vs baseline: 1.5938x; 1.5938x over previous
#include <cuda_runtime.h>
#include <cuda_bf16.h>
#include <cstdint>
#include <cstddef>

// Problem constants
#define NWIN   4096
#define TT     49
#define DIM    384
#define HEADS  12
#define HD     32
#define NQKV   1152
#define MROWS  (NWIN * TT)            // 200704
#define SCALE  0.17677669529663687f
#define EPS    1e-6f

#define AST    40                     // smem row stride in bf16 elems (80 B)
#define STAGEB (128 * AST * 2)        // 10240 bytes per stage per operand

// ---------------------------------------------------------------------------
// Scratch (device globals; no allocations allowed)
// ---------------------------------------------------------------------------
__device__ float         g_qkv[(size_t)MROWS * NQKV];   // 925 MB fp32
__device__ __nv_bfloat16 g_xhi[(size_t)MROWS * DIM];
__device__ __nv_bfloat16 g_xlo[(size_t)MROWS * DIM];
__device__ __nv_bfloat16 g_chi[(size_t)MROWS * DIM];
__device__ __nv_bfloat16 g_clo[(size_t)MROWS * DIM];
__device__ __nv_bfloat16 g_whi[NQKV * DIM];
__device__ __nv_bfloat16 g_wlo[NQKV * DIM];
__device__ __nv_bfloat16 g_phi[DIM * DIM];
__device__ __nv_bfloat16 g_plo[DIM * DIM];
__device__ float         g_biasg[HEADS * TT * TT];

// ---------------------------------------------------------------------------
// PTX helpers (baseline sm_80+ ISA only — NO tcgen05 on this toolchain)
// ---------------------------------------------------------------------------
__device__ __forceinline__ uint32_t smem_u32(const void* p) {
    uint32_t a;
    asm("{ .reg .u64 t; cvta.to.shared.u64 t, %1; cvt.u32.u64 %0, t; }"
        : "=r"(a) : "l"(p));
    return a;
}
__device__ __forceinline__ void cp_async16(uint32_t dst, const void* src) {
    asm volatile("cp.async.cg.shared.global [%0], [%1], 16;"
                 :: "r"(dst), "l"(src) : "memory");
}
__device__ __forceinline__ void ldsm4(uint32_t& r0, uint32_t& r1,
                                      uint32_t& r2, uint32_t& r3, uint32_t a) {
    asm volatile("ldmatrix.sync.aligned.m8n8.x4.shared.b16 {%0,%1,%2,%3}, [%4];"
                 : "=r"(r0), "=r"(r1), "=r"(r2), "=r"(r3) : "r"(a));
}
__device__ __forceinline__ void mma16816(float* d, const uint32_t* a,
                                         const uint32_t* b) {
    asm volatile(
        "mma.sync.aligned.m16n8k16.row.col.f32.bf16.bf16.f32 "
        "{%0,%1,%2,%3}, {%4,%5,%6,%7}, {%8,%9}, {%0,%1,%2,%3};"
        : "+f"(d[0]), "+f"(d[1]), "+f"(d[2]), "+f"(d[3])
        : "r"(a[0]), "r"(a[1]), "r"(a[2]), "r"(a[3]), "r"(b[0]), "r"(b[1]));
}

// ---------------------------------------------------------------------------
// HMMA GEMM: C[M,N] = sum over 3 products { Ahi*Bhi, Ahi*Blo, Alo*Bhi }
// A[M,K], B[N,K] both K-contiguous bf16. fp32 accum. BM=BN=128, BK=32.
// 8 warps: 2(M) x 4(N), warp tile 64x32 via m16n8k16 frags.
// ---------------------------------------------------------------------------
template<bool ADD_BIAS>
__global__ __launch_bounds__(256, 2)
void gemm_hmma3(const __nv_bfloat16* __restrict__ Ah,
                const __nv_bfloat16* __restrict__ Al,
                const __nv_bfloat16* __restrict__ Bh,
                const __nv_bfloat16* __restrict__ Bl,
                const float* __restrict__ bias, float* __restrict__ C,
                int M, int N, int K) {
    __shared__ __nv_bfloat16 As[2][128 * AST];
    __shared__ __nv_bfloat16 Bs[2][128 * AST];

    const int tid  = threadIdx.x;
    const int wid  = tid >> 5, lane = tid & 31;
    const int bm   = blockIdx.y * 128, bn = blockIdx.x * 128;
    const int wm   = (wid >> 2) * 64,  wn = (wid & 3) * 32;

    float acc[4][4][4];
#pragma unroll
    for (int i = 0; i < 4; i++)
#pragma unroll
        for (int j = 0; j < 4; j++)
#pragma unroll
            for (int r = 0; r < 4; r++) acc[i][j][r] = 0.f;

    const __nv_bfloat16* Aps[3] = {Ah, Ah, Al};
    const __nv_bfloat16* Bps[3] = {Bh, Bl, Bh};
    const int nkc = K >> 5;          // 12 for K=384
    const int nch = 3 * nkc;         // 36

    const uint32_t sA = smem_u32(As);
    const uint32_t sB = smem_u32(Bs);

    // load coords: thread -> (row, 16B-half); 2 lines each of A and B per thread
    const int lrow = tid >> 2;       // 0..63
    const int lhf  = tid & 3;        // 0..3 (x8 bf16)

    // ldmatrix lane address components
    const int m_l  = (lane & 7) + ((lane >> 3) & 1) * 8;
    const int kb_l = (lane >> 4) * 8;
    // B-frag lane components
    const int bn_l = lane >> 2;      // n within 8
    const int bk_l = (lane & 3) * 2; // k pair

#define PREFETCH(c, s)                                                         \
    do {                                                                       \
        int ph = (c) / nkc;                                                    \
        int kc = ((c) - ph * nkc) * 32;                                        \
        const __nv_bfloat16* Ag = Aps[ph];                                     \
        const __nv_bfloat16* Bg = Bps[ph];                                     \
        _Pragma("unroll")                                                      \
        for (int j = 0; j < 2; j++) {                                          \
            int row = lrow + j * 64;                                           \
            uint32_t doff = (uint32_t)(s) * STAGEB + (row * AST + lhf * 8) * 2;\
            cp_async16(sA + doff, Ag + (size_t)(bm + row) * K + kc + lhf * 8); \
            cp_async16(sB + doff, Bg + (size_t)(bn + row) * K + kc + lhf * 8); \
        }                                                                      \
        asm volatile("cp.async.commit_group;" ::: "memory");                   \
    } while (0)

    PREFETCH(0, 0);

    for (int c = 0; c < nch; c++) {
        if (c + 1 < nch) {
            PREFETCH(c + 1, (c + 1) & 1);
            asm volatile("cp.async.wait_group 1;" ::: "memory");
        } else {
            asm volatile("cp.async.wait_group 0;" ::: "memory");
        }
        __syncthreads();

        const uint32_t aBase = sA + (uint32_t)(c & 1) * STAGEB;
        const uint32_t bBase = sB + (uint32_t)(c & 1) * STAGEB;
#pragma unroll
        for (int ks = 0; ks < 2; ks++) {
            const int k0 = ks * 16;
            uint32_t a[4][4], b[4][2];
#pragma unroll
            for (int mf = 0; mf < 4; mf++) {
                int m = wm + mf * 16 + m_l;
                ldsm4(a[mf][0], a[mf][1], a[mf][2], a[mf][3],
                      aBase + (m * AST + k0 + kb_l) * 2);
            }
#pragma unroll
            for (int nf = 0; nf < 4; nf++) {
                int n = wn + nf * 8 + bn_l;
                uint32_t addr = bBase + (n * AST + k0 + bk_l) * 2;
                asm volatile("ld.shared.b32 %0, [%1];" : "=r"(b[nf][0]) : "r"(addr));
                asm volatile("ld.shared.b32 %0, [%1];" : "=r"(b[nf][1]) : "r"(addr + 16));
            }
#pragma unroll
            for (int mf = 0; mf < 4; mf++)
#pragma unroll
                for (int nf = 0; nf < 4; nf++)
                    mma16816(acc[mf][nf], a[mf], b[nf]);
        }
        __syncthreads();
    }
#undef PREFETCH

    // epilogue: D frag layout: c0,c1 at (row l/4, col 2*(l%4)), c2,c3 at row+8
#pragma unroll
    for (int mf = 0; mf < 4; mf++) {
        int m0 = bm + wm + mf * 16 + (lane >> 2);
#pragma unroll
        for (int nf = 0; nf < 4; nf++) {
            int n0 = bn + wn + nf * 8 + (lane & 3) * 2;
            float bx = 0.f, by = 0.f;
            if (ADD_BIAS) { bx = bias[n0]; by = bias[n0 + 1]; }
            float2 v0 = make_float2(acc[mf][nf][0] + bx, acc[mf][nf][1] + by);
            float2 v1 = make_float2(acc[mf][nf][2] + bx, acc[mf][nf][3] + by);
            *(float2*)&C[(size_t)m0 * N + n0]       = v0;
            *(float2*)&C[(size_t)(m0 + 8) * N + n0] = v1;
        }
    }
}

// ---------------------------------------------------------------------------
// fp32 -> bf16 hi/lo split
// ---------------------------------------------------------------------------
__global__ void split_kernel(const float* __restrict__ x,
                             __nv_bfloat16* __restrict__ hi,
                             __nv_bfloat16* __restrict__ lo, int n4) {
    int i = blockIdx.x * blockDim.x + threadIdx.x;
    if (i < n4) {
        float4 v = ((const float4*)x)[i];
        __nv_bfloat16 h0 = __float2bfloat16(v.x), h1 = __float2bfloat16(v.y);
        __nv_bfloat16 h2 = __float2bfloat16(v.z), h3 = __float2bfloat16(v.w);
        __nv_bfloat16 l0 = __float2bfloat16(v.x - __bfloat162float(h0));
        __nv_bfloat16 l1 = __float2bfloat16(v.y - __bfloat162float(h1));
        __nv_bfloat16 l2 = __float2bfloat16(v.z - __bfloat162float(h2));
        __nv_bfloat16 l3 = __float2bfloat16(v.w - __bfloat162float(h3));
        ((__nv_bfloat162*)hi)[2 * i]     = __halves2bfloat162(h0, h1);
        ((__nv_bfloat162*)hi)[2 * i + 1] = __halves2bfloat162(h2, h3);
        ((__nv_bfloat162*)lo)[2 * i]     = __halves2bfloat162(l0, l1);
        ((__nv_bfloat162*)lo)[2 * i + 1] = __halves2bfloat162(l2, l3);
    }
}

// ---------------------------------------------------------------------------
// bias gather
// ---------------------------------------------------------------------------
__global__ void gather_bias_kernel(const float* __restrict__ bt,
                                   const int* __restrict__ ri,
                                   float* __restrict__ ob) {
    int idx = blockIdx.x * blockDim.x + threadIdx.x;
    if (idx < HEADS * TT * TT) {
        int h = idx / (TT * TT);
        int p = idx - h * (TT * TT);
        ob[idx] = bt[ri[p] * HEADS + h];
    }
}

// ---------------------------------------------------------------------------
// Fused attention (fp32), writes ctx as bf16 hi/lo for the proj GEMM
// ---------------------------------------------------------------------------
__global__ __launch_bounds__(64)
void win_attn_kernel(const float* __restrict__ qkv,
                     const float* __restrict__ qn_w,
                     const float* __restrict__ kn_w,
                     const float* __restrict__ biasg,
                     __nv_bfloat16* __restrict__ chi,
                     __nv_bfloat16* __restrict__ clo) {
    const int b = blockIdx.x;
    const int h = blockIdx.y;
    const int tid = threadIdx.x;

    __shared__ float qs[TT][36];
    __shared__ float ks[TT][36];
    __shared__ float vs[TT][36];
    __shared__ float S[TT][TT];
    __shared__ float nwq[HD], nwk[HD];

    if (tid < HD) { nwq[tid] = qn_w[tid]; nwk[tid] = kn_w[tid]; }

    const float* base = qkv + (size_t)b * TT * NQKV + h * HD;
    for (int v4 = tid; v4 < TT * 8; v4 += 64) {
        int i = v4 >> 3, dv = v4 & 7;
        const float* rp = base + (size_t)i * NQKV + dv * 4;
        *(float4*)&qs[i][dv * 4] = *(const float4*)(rp);
        *(float4*)&ks[i][dv * 4] = *(const float4*)(rp + DIM);
        *(float4*)&vs[i][dv * 4] = *(const float4*)(rp + 2 * DIM);
    }
    __syncthreads();

    float qreg[HD];
    if (tid < TT) {
        float ssq = 0.f, ssk = 0.f;
#pragma unroll
        for (int d = 0; d < HD; d++) {
            float q = qs[tid][d]; qreg[d] = q; ssq += q * q;
            float k = ks[tid][d]; ssk += k * k;
        }
        float rq = rsqrtf(ssq * (1.f / HD) + EPS);
        float rk = rsqrtf(ssk * (1.f / HD) + EPS);
#pragma unroll
        for (int d = 0; d < HD; d++) {
            qreg[d] = qreg[d] * rq * nwq[d];
            ks[tid][d] *= rk * nwk[d];
        }
    }
    __syncthreads();

    if (tid < TT) {
        const float* brow = biasg + ((size_t)h * TT + tid) * TT;
        float mx = -1e30f;
        for (int j = 0; j < TT; j++) {
            float s = 0.f;
#pragma unroll
            for (int dv = 0; dv < 8; dv++) {
                float4 kk = *(const float4*)&ks[j][dv * 4];
                s += qreg[dv * 4]     * kk.x + qreg[dv * 4 + 1] * kk.y
                   + qreg[dv * 4 + 2] * kk.z + qreg[dv * 4 + 3] * kk.w;
            }
            s = s * SCALE + brow[j];
            S[tid][j] = s;
            mx = fmaxf(mx, s);
        }
        float sum = 0.f;
        for (int j = 0; j < TT; j++) {
            float e = __expf(S[tid][j] - mx);
            S[tid][j] = e;
            sum += e;
        }
        float inv = 1.f / sum;

        float o[HD];
#pragma unroll
        for (int d = 0; d < HD; d++) o[d] = 0.f;
        for (int j = 0; j < TT; j++) {
            float p = S[tid][j];
#pragma unroll
            for (int dv = 0; dv < 8; dv++) {
                float4 vv = *(const float4*)&vs[j][dv * 4];
                o[dv * 4]     += p * vv.x; o[dv * 4 + 1] += p * vv.y;
                o[dv * 4 + 2] += p * vv.z; o[dv * 4 + 3] += p * vv.w;
            }
        }
        size_t co = ((size_t)b * TT + tid) * DIM + h * HD;
#pragma unroll
        for (int dv = 0; dv < 16; dv++) {
            float a = o[dv * 2]     * inv;
            float c = o[dv * 2 + 1] * inv;
            __nv_bfloat16 ha = __float2bfloat16(a), hc = __float2bfloat16(c);
            __nv_bfloat16 la = __float2bfloat16(a - __bfloat162float(ha));
            __nv_bfloat16 lc = __float2bfloat16(c - __bfloat162float(hc));
            *(__nv_bfloat162*)(chi + co + dv * 2) = __halves2bfloat162(ha, hc);
            *(__nv_bfloat162*)(clo + co + dv * 2) = __halves2bfloat162(la, lc);
        }
    }
}

// ---------------------------------------------------------------------------
// Launch
// ---------------------------------------------------------------------------
extern "C" void kernel_launch(void* const* d_in, const int* in_sizes, int n_in,
                              void* d_out, int out_size) {
    const float* x          = (const float*)d_in[0];
    const float* qkv_w      = (const float*)d_in[1];
    const float* q_norm_w   = (const float*)d_in[2];
    const float* k_norm_w   = (const float*)d_in[3];
    const float* proj_w     = (const float*)d_in[4];
    const float* proj_b     = (const float*)d_in[5];
    const float* bias_table = (const float*)d_in[6];
    const int*   rel_index  = (const int*)d_in[7];
    float* out = (float*)d_out;

    float *qkvb, *biasb;
    __nv_bfloat16 *xhi, *xlo, *chi, *clo, *whi, *wlo, *phi, *plo;
    cudaGetSymbolAddress((void**)&qkvb,  g_qkv);
    cudaGetSymbolAddress((void**)&biasb, g_biasg);
    cudaGetSymbolAddress((void**)&xhi, g_xhi);  cudaGetSymbolAddress((void**)&xlo, g_xlo);
    cudaGetSymbolAddress((void**)&chi, g_chi);  cudaGetSymbolAddress((void**)&clo, g_clo);
    cudaGetSymbolAddress((void**)&whi, g_whi);  cudaGetSymbolAddress((void**)&wlo, g_wlo);
    cudaGetSymbolAddress((void**)&phi, g_phi);  cudaGetSymbolAddress((void**)&plo, g_plo);

    // bias gather
    gather_bias_kernel<<<(HEADS * TT * TT + 255) / 256, 256>>>(bias_table, rel_index, biasb);

    // splits
    {
        int n4 = (MROWS * DIM) / 4;
        split_kernel<<<(n4 + 255) / 256, 256>>>(x, xhi, xlo, n4);
        int w4 = (NQKV * DIM) / 4;
        split_kernel<<<(w4 + 255) / 256, 256>>>(qkv_w, whi, wlo, w4);
        int p4 = (DIM * DIM) / 4;
        split_kernel<<<(p4 + 255) / 256, 256>>>(proj_w, phi, plo, p4);
    }

    // qkv = x @ qkv_w^T  (HMMA, 3-product bf16)
    {
        dim3 grid(NQKV / 128, MROWS / 128);
        gemm_hmma3<false><<<grid, 256>>>(xhi, xlo, whi, wlo, nullptr, qkvb,
                                         MROWS, NQKV, DIM);
    }

    // fused windowed attention -> ctx (bf16 hi/lo)
    {
        dim3 grid(NWIN, HEADS);
        win_attn_kernel<<<grid, 64>>>(qkvb, q_norm_w, k_norm_w, biasb, chi, clo);
    }

    // out = ctx @ proj_w^T + proj_b
    {
        dim3 grid(DIM / 128, MROWS / 128);
        gemm_hmma3<true><<<grid, 256>>>(chi, clo, phi, plo, proj_b, out,
                                        MROWS, DIM, DIM);
    }
}